// round 10
// baseline (speedup 1.0000x reference)
#include <cuda_runtime.h>
#include <math.h>

// Problem constants (fixed by setup_inputs)
#define BB    2
#define NN    2048
#define FIN   256
#define CC    64              // feature width of both layers (8 heads * 8 = 64, Fout = 64)
#define MM    (BB*NN)         // 4096 rows
#define EMAX  32768
#define CAP   64              // per-node adjacency bucket capacity (Poisson(16) -> safe)
#define WBS   (CAP+4)         // weight-buffer stride: bank = 4*l8+g, conflict-free
#define ALPHA 0.2f            // leaky_relu slope
#define NBLK  296             // 2 blocks/SM on >=148 SMs -> all resident, barrier is safe
#define NWARP (NBLK*8)

// ---------------- scratch (device globals; no allocation allowed) ----------------
static __device__ __align__(16) float g_h1[MM*CC];
static __device__ __align__(16) float g_x1[MM*CC];
static __device__ __align__(16) float g_h2[MM*CC];
static __device__ __align__(16) float g_pre[MM*CC];
static __device__ float g_s1a[8*MM];
static __device__ float g_s2a[8*MM];
static __device__ float g_s1b[MM];
static __device__ float g_s2b[MM];
static __device__ int g_deg[NN];        // zeros at load; re-zeroed in the last phase each call
static __device__ int g_adj[NN*CAP];    // bucketed adjacency (targets), 512 KB

// grid barrier state (monotonic generation; survives graph replays)
static __device__ unsigned g_arrive = 0;
static __device__ volatile unsigned g_gen = 0;

__device__ __forceinline__ void grid_sync() {
    __syncthreads();
    if (threadIdx.x == 0) {
        __threadfence();                       // release phase writes
        unsigned gen = g_gen;
        if (atomicAdd(&g_arrive, 1) == NBLK - 1) {
            atomicExch(&g_arrive, 0);
            __threadfence();
            g_gen = gen + 1;                   // single writer; volatile store
        } else {
            while (g_gen == gen) { }
        }
    }
    __syncthreads();
}

union SmemU {
    struct { float As[16][64]; float Ws[64][64]; float Cs[16][64]; } g;  // 24 KB
    struct { int ts[8][CAP]; float w[8][8*WBS]; } a;                     // 19 KB
    struct { float2 red[256]; } l;                                       //  2 KB
};

// ---------------- GEMM tile: C[16 x 64] = A[16 x K] * W[K x 64] + score epilogue ----
// 256 threads; thread = 1x4 micro tile (ty = row 0..15, tx = col group 0..15).
// LAYER==1: K=256, W repacked inline from W_h [8,256,8]; LAYER==2: K=64, W = W_o.
template<int LAYER>
__device__ __forceinline__ void gemm_tile(int tile,
                                          const float* __restrict__ A,
                                          const float* __restrict__ Wraw,
                                          const float* __restrict__ avec,
                                          float* __restrict__ C,
                                          float* __restrict__ s1,
                                          float* __restrict__ s2,
                                          SmemU& sm) {
    const int K = (LAYER == 1) ? FIN : CC;
    int tid = threadIdx.x;
    int tx = tid & 15;
    int ty = tid >> 4;
    int m0 = tile * 16;
    float acc[4] = {};
    for (int k0 = 0; k0 < K; k0 += 64) {
        // stage A tile: 256 float4, 1 per thread (coalesced 256B rows)
        *reinterpret_cast<float4*>(&sm.g.As[ty][tx*4]) =
            *reinterpret_cast<const float4*>(&A[(m0 + ty) * K + k0 + tx*4]);
        // stage W tile: 1024 float4, 4 per thread
        #pragma unroll
        for (int v = 0; v < 4; v++) {
            int idx = tid + v*256;
            int r = idx >> 4, c4 = idx & 15;
            float4 w4;
            if (LAYER == 1) {
                int hh = c4 >> 1, o4 = (c4 & 1) * 4;   // W_h[h][f][o], 16B-aligned groups
                w4 = *reinterpret_cast<const float4*>(&Wraw[hh*(FIN*8) + (k0 + r)*8 + o4]);
            } else {
                w4 = *reinterpret_cast<const float4*>(&Wraw[(k0 + r)*64 + c4*4]);
            }
            *reinterpret_cast<float4*>(&sm.g.Ws[r][c4*4]) = w4;
        }
        __syncthreads();
        #pragma unroll 16
        for (int kk = 0; kk < 64; kk++) {
            float a0 = sm.g.As[ty][kk];
            float4 b4 = *reinterpret_cast<const float4*>(&sm.g.Ws[kk][tx*4]);
            acc[0] = fmaf(a0, b4.x, acc[0]);
            acc[1] = fmaf(a0, b4.y, acc[1]);
            acc[2] = fmaf(a0, b4.z, acc[2]);
            acc[3] = fmaf(a0, b4.w, acc[3]);
        }
        __syncthreads();
    }
    float4 o4 = make_float4(acc[0], acc[1], acc[2], acc[3]);
    *reinterpret_cast<float4*>(&C[(m0 + ty) * CC + tx*4]) = o4;
    *reinterpret_cast<float4*>(&sm.g.Cs[ty][tx*4]) = o4;
    __syncthreads();
    // score epilogue: 16 threads per row (r = ty, q = tx)
    int m = m0 + ty;
    if (LAYER == 1) {
        if (tx < 8) {       // thread owns head tx
            float d1 = 0.f, d2 = 0.f;
            #pragma unroll
            for (int o = 0; o < 8; o++) {
                float v = sm.g.Cs[ty][tx*8 + o];
                d1 = fmaf(v, avec[tx*16 + o],     d1);
                d2 = fmaf(v, avec[tx*16 + 8 + o], d2);
            }
            s1[tx*MM + m] = d1;
            s2[tx*MM + m] = d2;
        }
    } else {
        float d1 = 0.f, d2 = 0.f;
        #pragma unroll
        for (int o = 0; o < 4; o++) {
            float v = sm.g.Cs[ty][tx*4 + o];
            d1 = fmaf(v, avec[tx*4 + o],      d1);
            d2 = fmaf(v, avec[64 + tx*4 + o], d2);
        }
        #pragma unroll
        for (int off = 8; off; off >>= 1) {
            d1 += __shfl_down_sync(0xffffffffu, d1, off, 16);
            d2 += __shfl_down_sync(0xffffffffu, d2, off, 16);
        }
        if (tx == 0) { s1[m] = d1; s2[m] = d2; }
    }
    __syncthreads();
}

// ---------------- edge-softmax aggregation for one row (one warp) ----------------
// Score passes: GS = OW/2 lanes per head compute e/w in parallel -> smem.
// Gather: 4 groups x 8 lanes; group g handles edges g, g+4, ...; lane l8 owns
// features l8*8..+7 (2x float4 -> full 256B h row per group). Reduce: xor 8,16.
// Dedup: duplicates count once (dense-cell .set semantics) -> ts=-1, w=0.
template<int HH, int OW, bool DOELU>
__device__ __forceinline__ void agg_row(int gw,
                                        const float* __restrict__ h,
                                        const float* __restrict__ s1,
                                        const float* __restrict__ s2,
                                        const float* __restrict__ bias,
                                        float* __restrict__ o,
                                        int* ts, float* wbase) {
    const int GS = OW / 2;                 // 4 (layer1) / 32 (layer2)
    int lane = threadIdx.x & 31;
    int b    = gw >> 11;                   // / NN
    int src  = gw & (NN - 1);
    int g    = lane >> 3;
    int l8   = lane & 7;
    const int hh_s = (OW == 8) ? (lane >> 2) : 0;
    int d = g_deg[src]; if (d > CAP) d = CAP;
    float acc[8] = {};
    float sw = 0.f;
    if (d == 0) {
        // empty row -> uniform 1/N softmax -> column mean of h (rare path)
        const float* hb = h + b * NN * CC + l8 * 8;
        for (int n = g; n < NN; n += 4) {
            float4 p = *reinterpret_cast<const float4*>(hb + n*CC);
            float4 q = *reinterpret_cast<const float4*>(hb + n*CC + 4);
            acc[0]+=p.x; acc[1]+=p.y; acc[2]+=p.z; acc[3]+=p.w;
            acc[4]+=q.x; acc[5]+=q.y; acc[6]+=q.z; acc[7]+=q.w;
        }
    } else {
        for (int j = lane; j < d; j += 32) ts[j] = g_adj[src*CAP + j];
        __syncwarp();
        if (d <= 32) {
            // O(1) dedup: keep first occurrence (lowest index)
            int t0 = (lane < d) ? ts[lane] : (-(int)lane - 1);  // unique sentinels
            unsigned mset = __match_any_sync(0xffffffffu, t0);
            bool dup0 = (lane < d) && ((mset & ((1u << lane) - 1u)) != 0u);
            __syncwarp();
            if (dup0) ts[lane] = -1;
        } else {
            int  t0 = -1, t1 = -1;
            bool dup0 = false, dup1 = false;
            if (lane < d)      { t0 = ts[lane];      for (int i = 0; i < lane;      i++) dup0 |= (ts[i] == t0); }
            if (lane + 32 < d) { t1 = ts[lane + 32]; for (int i = 0; i < lane + 32; i++) dup1 |= (ts[i] == t1); }
            __syncwarp();
            if (dup0) ts[lane]      = -1;
            if (dup1) ts[lane + 32] = -1;
        }
        __syncwarp();
        float sv = s1[hh_s*MM + gw];
        const float* s2h = s2 + hh_s*MM + b*NN;
        float* wb = wbase + hh_s * WBS;
        // pass 1: e_j -> smem, subgroup max (dups excluded)
        float mx = -INFINITY;
        for (int j = (lane & (GS - 1)); j < d; j += GS) {
            int t = ts[j];
            int tt = t < 0 ? 0 : t;
            float e = sv + s2h[tt];
            e = e > 0.f ? e : ALPHA * e;
            wb[j] = e;
            if (t >= 0) mx = fmaxf(mx, e);
        }
        #pragma unroll
        for (int off = GS >> 1; off; off >>= 1)
            mx = fmaxf(mx, __shfl_xor_sync(0xffffffffu, mx, off));
        // pass 2: w_j = exp(e_j - mx), subgroup sum
        for (int j = (lane & (GS - 1)); j < d; j += GS) {
            float w = (ts[j] >= 0) ? __expf(wb[j] - mx) : 0.f;
            wb[j] = w;
            sw += w;
        }
        #pragma unroll
        for (int off = GS >> 1; off; off >>= 1)
            sw += __shfl_xor_sync(0xffffffffu, sw, off);
        __syncwarp();
        // gather: group g takes edges j = g, g+4, ...
        const float* hb = h + b * NN * CC + l8 * 8;
        const float* wme = wbase + (HH == 8 ? l8 : 0) * WBS;
        for (int j = g; j < d; j += 4) {
            int t = ts[j];
            int tt = t < 0 ? 0 : t;
            float w = wme[j];
            float4 p = *reinterpret_cast<const float4*>(hb + tt*CC);
            float4 q = *reinterpret_cast<const float4*>(hb + tt*CC + 4);
            acc[0] = fmaf(w, p.x, acc[0]); acc[1] = fmaf(w, p.y, acc[1]);
            acc[2] = fmaf(w, p.z, acc[2]); acc[3] = fmaf(w, p.w, acc[3]);
            acc[4] = fmaf(w, q.x, acc[4]); acc[5] = fmaf(w, q.y, acc[5]);
            acc[6] = fmaf(w, q.z, acc[6]); acc[7] = fmaf(w, q.w, acc[7]);
        }
        __syncwarp();
    }
    #pragma unroll
    for (int off = 8; off <= 16; off <<= 1)
        #pragma unroll
        for (int i = 0; i < 8; i++)
            acc[i] += __shfl_xor_sync(0xffffffffu, acc[i], off);
    float inv;
    if (d == 0)          inv = 1.0f / NN;
    else if (OW == 8)    inv = 1.0f / __shfl_sync(0xffffffffu, sw, 4*l8);
    else                 inv = 1.0f / sw;
    if (g == 0) {
        float4 bz0 = *reinterpret_cast<const float4*>(bias + l8*8);
        float4 bz1 = *reinterpret_cast<const float4*>(bias + l8*8 + 4);
        float z[8];
        z[0]=acc[0]*inv+bz0.x; z[1]=acc[1]*inv+bz0.y; z[2]=acc[2]*inv+bz0.z; z[3]=acc[3]*inv+bz0.w;
        z[4]=acc[4]*inv+bz1.x; z[5]=acc[5]*inv+bz1.y; z[6]=acc[6]*inv+bz1.z; z[7]=acc[7]*inv+bz1.w;
        if (DOELU) {
            #pragma unroll
            for (int i = 0; i < 8; i++) z[i] = z[i] > 0.f ? z[i] : expm1f(z[i]);
        }
        *reinterpret_cast<float4*>(&o[gw*CC + l8*8])     = make_float4(z[0], z[1], z[2], z[3]);
        *reinterpret_cast<float4*>(&o[gw*CC + l8*8 + 4]) = make_float4(z[4], z[5], z[6], z[7]);
    }
}

// ---------------- log_softmax unit: (batch b, 2 features) over the node axis ----------
__device__ __forceinline__ void lsm_unit(int u, float* __restrict__ out, SmemU& sm) {
    int b  = u >> 5;
    int f0 = (u & 31) * 2;
    int t  = threadIdx.x;
    float2 v[8];
    float2 mx = make_float2(-INFINITY, -INFINITY);
    #pragma unroll
    for (int i = 0; i < 8; i++) {
        v[i] = *reinterpret_cast<const float2*>(&g_pre[(b*NN + i*256 + t) * CC + f0]);
        mx.x = fmaxf(mx.x, v[i].x); mx.y = fmaxf(mx.y, v[i].y);
    }
    sm.l.red[t] = mx; __syncthreads();
    for (int s = 128; s; s >>= 1) {
        if (t < s) {
            float2 a = sm.l.red[t], c = sm.l.red[t + s];
            sm.l.red[t] = make_float2(fmaxf(a.x,c.x), fmaxf(a.y,c.y));
        }
        __syncthreads();
    }
    mx = sm.l.red[0];
    __syncthreads();
    float2 smv = make_float2(0.f, 0.f);
    #pragma unroll
    for (int i = 0; i < 8; i++) {
        smv.x += __expf(v[i].x - mx.x); smv.y += __expf(v[i].y - mx.y);
    }
    sm.l.red[t] = smv; __syncthreads();
    for (int s = 128; s; s >>= 1) {
        if (t < s) {
            float2 a = sm.l.red[t], c = sm.l.red[t + s];
            sm.l.red[t] = make_float2(a.x + c.x, a.y + c.y);
        }
        __syncthreads();
    }
    smv = sm.l.red[0];
    float2 l = make_float2(mx.x + logf(smv.x), mx.y + logf(smv.y));
    #pragma unroll
    for (int i = 0; i < 8; i++) {
        *reinterpret_cast<float2*>(&out[(b*NN + i*256 + t) * CC + f0]) =
            make_float2(v[i].x - l.x, v[i].y - l.y);
    }
    __syncthreads();
}

// ---------------- the single persistent kernel ----------------
__global__ void __launch_bounds__(256, 2) k_fused(
    const float* __restrict__ x, const int* __restrict__ edges,
    const float* __restrict__ Wh, const float* __restrict__ ah,
    const float* __restrict__ bh, const float* __restrict__ Wo,
    const float* __restrict__ ao, const float* __restrict__ bo,
    float* __restrict__ out, int E)
{
    __shared__ SmemU sm;
    int tid  = threadIdx.x;
    int warp = tid >> 5;

    // phase A: adjacency build (independent of gemm1) + gemm1 tiles
    {
        int e = blockIdx.x * 256 + tid;      // NBLK*256 = 75776 >= E
        if (e < E) {
            int s = edges[e], t = edges[E + e];
            int pos = atomicAdd(&g_deg[s], 1);
            if (pos < CAP) g_adj[s*CAP + pos] = t;
        }
    }
    for (int tile = blockIdx.x; tile < MM/16; tile += NBLK)
        gemm_tile<1>(tile, x, Wh, ah, g_h1, g_s1a, g_s2a, sm);
    grid_sync();

    // phase B: agg1 (8 heads x 8, + bias + ELU)
    for (int row = blockIdx.x*8 + warp; row < MM; row += NWARP)
        agg_row<8, 8, true>(row, g_h1, g_s1a, g_s2a, bh,
                            g_x1, sm.a.ts[warp], sm.a.w[warp]);
    grid_sync();

    // phase C: gemm2
    for (int tile = blockIdx.x; tile < MM/16; tile += NBLK)
        gemm_tile<2>(tile, g_x1, Wo, ao, g_h2, g_s1b, g_s2b, sm);
    grid_sync();

    // phase D: agg2 (1 head x 64, + bias)
    for (int row = blockIdx.x*8 + warp; row < MM; row += NWARP)
        agg_row<1, 64, false>(row, g_h2, g_s1b, g_s2b, bo,
                              g_pre, sm.a.ts[warp], sm.a.w[warp]);
    grid_sync();

    // phase E: log_softmax + restore g_deg = 0 for the next call
    {
        int gt = blockIdx.x * 256 + tid;
        if (gt < NN) g_deg[gt] = 0;
    }
    for (int u = blockIdx.x; u < BB*32; u += NBLK)
        lsm_unit(u, out, sm);
}

// ---------------- launch: ONE kernel ----------------
extern "C" void kernel_launch(void* const* d_in, const int* in_sizes, int n_in,
                              void* d_out, int out_size) {
    const float* x     = (const float*)d_in[0];
    const int*   edges = (const int*)  d_in[1];
    const float* Wh    = (const float*)d_in[2];
    const float* ah    = (const float*)d_in[3];
    const float* bh    = (const float*)d_in[4];
    const float* Wo    = (const float*)d_in[5];
    const float* ao    = (const float*)d_in[6];
    const float* bo    = (const float*)d_in[7];
    float* out = (float*)d_out;
    int E = in_sizes[1] / 2;
    if (E > EMAX) E = EMAX;   // defensive clamp; dataset uses E = 32768

    k_fused<<<NBLK, 256>>>(x, edges, Wh, ah, bh, Wo, ao, bo, out, E);
}

// round 11
// speedup vs baseline: 1.1469x; 1.1469x over previous
#include <cuda_runtime.h>
#include <math.h>

// Problem constants (fixed by setup_inputs)
#define BB    2
#define NN    2048
#define FIN   256
#define CC    64              // feature width of both layers (8 heads * 8 = 64, Fout = 64)
#define MM    (BB*NN)         // 4096 rows
#define EMAX  32768
#define CAP   64              // per-node adjacency bucket capacity (Poisson(16) -> safe)
#define WBS   (CAP+4)         // weight-buffer stride: bank = 4*l8+g, conflict-free
#define ALPHA 0.2f            // leaky_relu slope

// ---------------- scratch (device globals; no allocation allowed) ----------------
static __device__ __align__(16) float g_h1[MM*CC];
static __device__ __align__(16) float g_h2[MM*CC];
static __device__ __align__(16) float g_pre[MM*CC];
static __device__ float g_s1a[8*MM];
static __device__ float g_s2a[8*MM];
static __device__ float g_s1b[MM];
static __device__ float g_s2b[MM];
static __device__ int g_deg[NN];        // zeros at load; re-zeroed by k_lsm each call
static __device__ int g_adj[NN*CAP];    // bucketed adjacency (targets), 512 KB

// ---------------- k_gemm1: 16x64 tile of h1 = x @ W1 (+ adj build + head scores) ----
// 256 blocks x 256 threads; thread = 1x4 micro tile. W repacked inline from W_h [8,256,8].
__global__ void k_gemm1(const float* __restrict__ x, const float* __restrict__ Wh,
                        const float* __restrict__ ah,
                        const int* __restrict__ edges, int E) {
    __shared__ float As[16][64];
    __shared__ float Ws[64][64];
    __shared__ float Cs[16][64];
    int tid = threadIdx.x;
    // adjacency build prologue: 256*256 = 65536 >= E
    int e = blockIdx.x * 256 + tid;
    if (e < E) {
        int s = edges[e], t = edges[E + e];
        int pos = atomicAdd(&g_deg[s], 1);
        if (pos < CAP) g_adj[s*CAP + pos] = t;
    }
    int tx = tid & 15;
    int ty = tid >> 4;
    int m0 = blockIdx.x * 16;
    float acc[4] = {};
    for (int k0 = 0; k0 < FIN; k0 += 64) {
        *reinterpret_cast<float4*>(&As[ty][tx*4]) =
            *reinterpret_cast<const float4*>(&x[(m0 + ty) * FIN + k0 + tx*4]);
        #pragma unroll
        for (int v = 0; v < 4; v++) {
            int idx = tid + v*256;
            int r = idx >> 4, c4 = idx & 15;
            int hh = c4 >> 1, o4 = (c4 & 1) * 4;   // W_h[h][f][o], 16B-aligned groups
            *reinterpret_cast<float4*>(&Ws[r][c4*4]) =
                *reinterpret_cast<const float4*>(&Wh[hh*(FIN*8) + (k0 + r)*8 + o4]);
        }
        __syncthreads();
        #pragma unroll 16
        for (int kk = 0; kk < 64; kk++) {
            float a0 = As[ty][kk];
            float4 b4 = *reinterpret_cast<const float4*>(&Ws[kk][tx*4]);
            acc[0] = fmaf(a0, b4.x, acc[0]);
            acc[1] = fmaf(a0, b4.y, acc[1]);
            acc[2] = fmaf(a0, b4.z, acc[2]);
            acc[3] = fmaf(a0, b4.w, acc[3]);
        }
        __syncthreads();
    }
    float4 o4 = make_float4(acc[0], acc[1], acc[2], acc[3]);
    *reinterpret_cast<float4*>(&g_h1[(m0 + ty) * CC + tx*4]) = o4;
    *reinterpret_cast<float4*>(&Cs[ty][tx*4]) = o4;
    __syncthreads();
    // head-score epilogue: thread (ty, tx<8) owns head tx of row m0+ty
    if (tx < 8) {
        int m = m0 + ty;
        float d1 = 0.f, d2 = 0.f;
        #pragma unroll
        for (int o = 0; o < 8; o++) {
            float v = Cs[ty][tx*8 + o];
            d1 = fmaf(v, ah[tx*16 + o],     d1);
            d2 = fmaf(v, ah[tx*16 + 8 + o], d2);
        }
        g_s1a[tx*MM + m] = d1;
        g_s2a[tx*MM + m] = d2;
    }
}

// ---------------- agg core: edge-softmax aggregation for one row (one warp) --------
// Score passes: GS = OW/2 lanes per head compute e/w in parallel -> smem.
// Gather: 4 groups x 8 lanes; group g handles edges g, g+4, ...; lane l8 owns
// features l8*8..+7 (2x float4 -> full 256B h row per group). Reduce: xor 8,16.
// Dedup: duplicates count once (dense-cell .set semantics) -> ts=-1, w=0.
// Result (bias added, optional ELU) written to dst[l8*8..+7] by g==0 lanes.
// dst may be global or shared (generic pointer).
template<int HH, int OW, bool DOELU>
__device__ __forceinline__ void agg_core(int gw,
                                         const float* __restrict__ h,
                                         const float* __restrict__ s1,
                                         const float* __restrict__ s2,
                                         const float* __restrict__ bias,
                                         float* dst,
                                         int* ts, float* wbase) {
    const int GS = OW / 2;                 // 4 (layer1) / 32 (layer2)
    int lane = threadIdx.x & 31;
    int b    = gw >> 11;                   // / NN
    int src  = gw & (NN - 1);
    int g    = lane >> 3;
    int l8   = lane & 7;
    const int hh_s = (OW == 8) ? (lane >> 2) : 0;
    int d = g_deg[src]; if (d > CAP) d = CAP;
    float acc[8] = {};
    float sw = 0.f;
    if (d == 0) {
        // empty row -> uniform 1/N softmax -> column mean of h (rare path)
        const float* hb = h + b * NN * CC + l8 * 8;
        for (int n = g; n < NN; n += 4) {
            float4 p = *reinterpret_cast<const float4*>(hb + n*CC);
            float4 q = *reinterpret_cast<const float4*>(hb + n*CC + 4);
            acc[0]+=p.x; acc[1]+=p.y; acc[2]+=p.z; acc[3]+=p.w;
            acc[4]+=q.x; acc[5]+=q.y; acc[6]+=q.z; acc[7]+=q.w;
        }
    } else {
        for (int j = lane; j < d; j += 32) ts[j] = g_adj[src*CAP + j];
        __syncwarp();
        if (d <= 32) {
            // O(1) dedup: keep first occurrence (lowest index)
            int t0 = (lane < d) ? ts[lane] : (-(int)lane - 1);  // unique sentinels
            unsigned mset = __match_any_sync(0xffffffffu, t0);
            bool dup0 = (lane < d) && ((mset & ((1u << lane) - 1u)) != 0u);
            __syncwarp();
            if (dup0) ts[lane] = -1;
        } else {
            int  t0 = -1, t1 = -1;
            bool dup0 = false, dup1 = false;
            if (lane < d)      { t0 = ts[lane];      for (int i = 0; i < lane;      i++) dup0 |= (ts[i] == t0); }
            if (lane + 32 < d) { t1 = ts[lane + 32]; for (int i = 0; i < lane + 32; i++) dup1 |= (ts[i] == t1); }
            __syncwarp();
            if (dup0) ts[lane]      = -1;
            if (dup1) ts[lane + 32] = -1;
        }
        __syncwarp();
        float sv = s1[hh_s*MM + gw];
        const float* s2h = s2 + hh_s*MM + b*NN;
        float* wb = wbase + hh_s * WBS;
        // pass 1: e_j -> smem, subgroup max (dups excluded)
        float mx = -INFINITY;
        for (int j = (lane & (GS - 1)); j < d; j += GS) {
            int t = ts[j];
            int tt = t < 0 ? 0 : t;
            float e = sv + s2h[tt];
            e = e > 0.f ? e : ALPHA * e;
            wb[j] = e;
            if (t >= 0) mx = fmaxf(mx, e);
        }
        #pragma unroll
        for (int off = GS >> 1; off; off >>= 1)
            mx = fmaxf(mx, __shfl_xor_sync(0xffffffffu, mx, off));
        // pass 2: w_j = exp(e_j - mx), subgroup sum
        for (int j = (lane & (GS - 1)); j < d; j += GS) {
            float w = (ts[j] >= 0) ? __expf(wb[j] - mx) : 0.f;
            wb[j] = w;
            sw += w;
        }
        #pragma unroll
        for (int off = GS >> 1; off; off >>= 1)
            sw += __shfl_xor_sync(0xffffffffu, sw, off);
        __syncwarp();
        // gather: group g takes edges j = g, g+4, ...
        const float* hb = h + b * NN * CC + l8 * 8;
        const float* wme = wbase + (HH == 8 ? l8 : 0) * WBS;
        for (int j = g; j < d; j += 4) {
            int t = ts[j];
            int tt = t < 0 ? 0 : t;
            float w = wme[j];
            float4 p = *reinterpret_cast<const float4*>(hb + tt*CC);
            float4 q = *reinterpret_cast<const float4*>(hb + tt*CC + 4);
            acc[0] = fmaf(w, p.x, acc[0]); acc[1] = fmaf(w, p.y, acc[1]);
            acc[2] = fmaf(w, p.z, acc[2]); acc[3] = fmaf(w, p.w, acc[3]);
            acc[4] = fmaf(w, q.x, acc[4]); acc[5] = fmaf(w, q.y, acc[5]);
            acc[6] = fmaf(w, q.z, acc[6]); acc[7] = fmaf(w, q.w, acc[7]);
        }
        __syncwarp();
    }
    #pragma unroll
    for (int off = 8; off <= 16; off <<= 1)
        #pragma unroll
        for (int i = 0; i < 8; i++)
            acc[i] += __shfl_xor_sync(0xffffffffu, acc[i], off);
    float inv;
    if (d == 0)          inv = 1.0f / NN;
    else if (OW == 8)    inv = 1.0f / __shfl_sync(0xffffffffu, sw, 4*l8);
    else                 inv = 1.0f / sw;
    if (g == 0) {
        float4 bz0 = *reinterpret_cast<const float4*>(bias + l8*8);
        float4 bz1 = *reinterpret_cast<const float4*>(bias + l8*8 + 4);
        float z[8];
        z[0]=acc[0]*inv+bz0.x; z[1]=acc[1]*inv+bz0.y; z[2]=acc[2]*inv+bz0.z; z[3]=acc[3]*inv+bz0.w;
        z[4]=acc[4]*inv+bz1.x; z[5]=acc[5]*inv+bz1.y; z[6]=acc[6]*inv+bz1.z; z[7]=acc[7]*inv+bz1.w;
        if (DOELU) {
            #pragma unroll
            for (int i = 0; i < 8; i++) z[i] = z[i] > 0.f ? z[i] : expm1f(z[i]);
        }
        *reinterpret_cast<float4*>(dst + l8*8)     = make_float4(z[0], z[1], z[2], z[3]);
        *reinterpret_cast<float4*>(dst + l8*8 + 4) = make_float4(z[4], z[5], z[6], z[7]);
    }
}

// ---------------- k_agg1g2: agg1 (+bias+ELU) fused with gemm2 + layer-2 scores ------
// One warp per row. The x1 row never touches global memory: it is staged in smem and
// immediately contracted with Wo (smem-cached) into h2[row,:], plus s1b/s2b dots.
__global__ void k_agg1g2(const float* __restrict__ bh, const float* __restrict__ Wo,
                         const float* __restrict__ ao) {
    __shared__ float Wos[64][64];                  // 16 KB
    __shared__ float aos[128];
    __shared__ int   ts_all[8][CAP];
    __shared__ float w_all[8][8*WBS];
    __shared__ __align__(16) float zrow[8][64];
    int tid  = threadIdx.x;
    int warp = tid >> 5;
    int lane = tid & 31;
    // stage Wo (64x64) + ao (128)
    #pragma unroll
    for (int v = 0; v < 4; v++) {
        int idx = tid + v*256;
        int r = idx >> 4, c4 = idx & 15;
        *reinterpret_cast<float4*>(&Wos[r][c4*4]) =
            *reinterpret_cast<const float4*>(&Wo[r*64 + c4*4]);
    }
    if (tid < 32) *reinterpret_cast<float4*>(&aos[tid*4]) =
        *reinterpret_cast<const float4*>(&ao[tid*4]);
    __syncthreads();

    int row = blockIdx.x * 8 + warp;               // 512 blocks -> rows 0..4095
    agg_core<8, 8, true>(row, g_h1, g_s1a, g_s2a, bh,
                         zrow[warp], ts_all[warp], w_all[warp]);
    __syncwarp();
    // gemm2 row: lane owns output cols 2*lane, 2*lane+1
    float c0 = 0.f, c1 = 0.f;
    const float* zr = zrow[warp];
    #pragma unroll 16
    for (int k = 0; k < 64; k++) {
        float zk = zr[k];                          // broadcast LDS
        float2 wv = *reinterpret_cast<const float2*>(&Wos[k][2*lane]);
        c0 = fmaf(zk, wv.x, c0);
        c1 = fmaf(zk, wv.y, c1);
    }
    *reinterpret_cast<float2*>(&g_h2[row*CC + 2*lane]) = make_float2(c0, c1);
    // layer-2 scores: warp-reduced dots with ao[:64], ao[64:]
    float p1 = c0*aos[2*lane] + c1*aos[2*lane+1];
    float p2 = c0*aos[64+2*lane] + c1*aos[64+2*lane+1];
    #pragma unroll
    for (int off = 16; off; off >>= 1) {
        p1 += __shfl_xor_sync(0xffffffffu, p1, off);
        p2 += __shfl_xor_sync(0xffffffffu, p2, off);
    }
    if (lane == 0) { g_s1b[row] = p1; g_s2b[row] = p2; }
}

// ---------------- k_agg2: layer-2 aggregation (+bias) -> g_pre ----------------
__global__ void k_agg2(const float* __restrict__ bo) {
    __shared__ int   ts_all[8][CAP];
    __shared__ float w_all[8][WBS];
    int warp = threadIdx.x >> 5;
    int row  = blockIdx.x * 8 + warp;
    agg_core<1, 64, false>(row, g_h2, g_s1b, g_s2b, bo,
                           g_pre + row*CC, ts_all[warp], w_all[warp]);
}

// ---------------- k_lsm: log_softmax over node axis + deg re-zero ----------------
// 64 blocks: block = (batch b, 2 features) via float2; 256 threads x 8 rows.
__global__ void k_lsm(float* __restrict__ out) {
    int gt = blockIdx.x * blockDim.x + threadIdx.x;
    if (gt < NN) g_deg[gt] = 0;          // restore invariant for next call

    int b  = blockIdx.x >> 5;
    int f0 = (blockIdx.x & 31) * 2;
    int t  = threadIdx.x;
    float2 v[8];
    float2 mx = make_float2(-INFINITY, -INFINITY);
    #pragma unroll
    for (int i = 0; i < 8; i++) {
        v[i] = *reinterpret_cast<const float2*>(&g_pre[(b*NN + i*256 + t) * CC + f0]);
        mx.x = fmaxf(mx.x, v[i].x); mx.y = fmaxf(mx.y, v[i].y);
    }
    __shared__ float2 red[256];
    red[t] = mx; __syncthreads();
    for (int s = 128; s; s >>= 1) {
        if (t < s) {
            float2 a = red[t], c = red[t + s];
            red[t] = make_float2(fmaxf(a.x,c.x), fmaxf(a.y,c.y));
        }
        __syncthreads();
    }
    mx = red[0];
    __syncthreads();
    float2 sm = make_float2(0.f, 0.f);
    #pragma unroll
    for (int i = 0; i < 8; i++) {
        sm.x += __expf(v[i].x - mx.x); sm.y += __expf(v[i].y - mx.y);
    }
    red[t] = sm; __syncthreads();
    for (int s = 128; s; s >>= 1) {
        if (t < s) {
            float2 a = red[t], c = red[t + s];
            red[t] = make_float2(a.x + c.x, a.y + c.y);
        }
        __syncthreads();
    }
    sm = red[0];
    float2 l = make_float2(mx.x + logf(sm.x), mx.y + logf(sm.y));
    #pragma unroll
    for (int i = 0; i < 8; i++) {
        *reinterpret_cast<float2*>(&out[(b*NN + i*256 + t) * CC + f0]) =
            make_float2(v[i].x - l.x, v[i].y - l.y);
    }
}

// ---------------- launch: 4 kernels ----------------
extern "C" void kernel_launch(void* const* d_in, const int* in_sizes, int n_in,
                              void* d_out, int out_size) {
    const float* x     = (const float*)d_in[0];
    const int*   edges = (const int*)  d_in[1];
    const float* Wh    = (const float*)d_in[2];
    const float* ah    = (const float*)d_in[3];
    const float* bh    = (const float*)d_in[4];
    const float* Wo    = (const float*)d_in[5];
    const float* ao    = (const float*)d_in[6];
    const float* bo    = (const float*)d_in[7];
    float* out = (float*)d_out;
    int E = in_sizes[1] / 2;
    if (E > EMAX) E = EMAX;   // defensive clamp; dataset uses E = 32768

    k_gemm1 <<<MM/16, 256>>>(x, Wh, ah, edges, E);  // + adjacency build prologue
    k_agg1g2<<<MM/8,  256>>>(bh, Wo, ao);           // agg1 + fused gemm2 + scores
    k_agg2  <<<MM/8,  256>>>(bo);
    k_lsm   <<<BB*32, 256>>>(out);                  // + deg re-zero epilogue
}